// round 15
// baseline (speedup 1.0000x reference)
#include <cuda_runtime.h>
#include <cuda_fp16.h>
#include <cstdint>

#define N_NODES 100000
#define N_EDGES 1600000
#define D_FEAT 48
#define STRIDE 64                       // padded segment per node (max deg ~40)

#define NODES_PER_BLK 32
#define SEG_INTS (NODES_PER_BLK * STRIDE)   // 2048 staged indices / block

#define PITCH_U4 8                      // half rows padded 96B -> 128B (8 uint4)

// ---- static device scratch (no allocation allowed) ----
__device__ int   g_cur[N_NODES];            // cursor; after fill = beg + deg
__device__ int   g_csr[N_NODES * STRIDE];   // padded per-node src lists
__device__ uint4 g_buf0[N_NODES * PITCH_U4];  // half[N,48], 128B-aligned rows
__device__ uint4 g_buf1[N_NODES * PITCH_U4];

// ---------------------------------------------------------------------------
// Bucket build: init cursors, then atomic scatter. No histogram, no scan.
// ---------------------------------------------------------------------------
__global__ void init_cur_kernel() {
    int i = blockIdx.x * blockDim.x + threadIdx.x;
    if (i < N_NODES) g_cur[i] = i * STRIDE;
}

// 2 int4 quads (8 edges) per thread: 8 independent atomics in flight.
__global__ void fill_kernel(const int4* __restrict__ src4,
                            const int4* __restrict__ dst4, int n_quads) {
    int q0 = (blockIdx.x * blockDim.x + threadIdx.x) * 2;
    #pragma unroll
    for (int k = 0; k < 2; ++k) {
        int q = q0 + k;
        if (q < n_quads) {
            int4 s = src4[q];
            int4 d = dst4[q];
            g_csr[atomicAdd(&g_cur[d.x], 1)] = s.x;
            g_csr[atomicAdd(&g_cur[d.y], 1)] = s.y;
            g_csr[atomicAdd(&g_cur[d.z], 1)] = s.z;
            g_csr[atomicAdd(&g_cur[d.w], 1)] = s.w;
        }
    }
}

// ---------------------------------------------------------------------------
// Layer 1: fp32 features -> padded half buf (relu on store). fp32 accumulation.
// 32 nodes/block x 12 chunk-threads (proven geometry).
// ---------------------------------------------------------------------------
#define L1_THREADS (NODES_PER_BLK * 12)   // 384

__global__ void __launch_bounds__(L1_THREADS)
layer_f32_to_h(const float4* __restrict__ h, uint2* __restrict__ out) {
    __shared__ int s_idx[SEG_INTS];
    int node0 = blockIdx.x * NODES_PER_BLK;
    int tid = threadIdx.x;
    int nl = tid / 12, c = tid - nl * 12;
    int node = node0 + nl;
    int base = node0 * STRIDE;

    for (int i = tid; i < SEG_INTS; i += L1_THREADS)
        s_idx[i] = g_csr[base + i];
    __syncthreads();

    int beg = nl * STRIDE;              // block-relative
    int end = __ldg(&g_cur[node]) - base;

    float4 acc = make_float4(0.f, 0.f, 0.f, 0.f);
    #pragma unroll 4
    for (int j = beg; j < end; ++j) {
        int s = s_idx[j];
        float4 v = __ldg(h + (unsigned)s * 12 + c);
        acc.x += v.x; acc.y += v.y; acc.z += v.z; acc.w += v.w;
    }

    __half2 a = __floats2half2_rn(fmaxf(acc.x, 0.f), fmaxf(acc.y, 0.f));
    __half2 b = __floats2half2_rn(fmaxf(acc.z, 0.f), fmaxf(acc.w, 0.f));
    uint2 u;
    u.x = *reinterpret_cast<unsigned*>(&a);
    u.y = *reinterpret_cast<unsigned*>(&b);
    out[(unsigned)node * (PITCH_U4 * 2) + c] = u;   // pitch = 16 uint2 / row
}

// ---------------------------------------------------------------------------
// Layers 2/3: padded half in, HADD2 accumulation.
// FINAL=false -> HMAX2 relu + raw half store; FINAL=true -> fp32 out (unpadded).
// 32 nodes/block x 6 chunk-threads. One aligned 128B line per gathered row.
// ---------------------------------------------------------------------------
#define LH_THREADS (NODES_PER_BLK * 6)    // 192

template <bool FINAL>
__global__ void __launch_bounds__(LH_THREADS)
layer_h(const uint4* __restrict__ h, uint4* __restrict__ outh,
        float4* __restrict__ outf) {
    __shared__ int s_idx[SEG_INTS];
    int node0 = blockIdx.x * NODES_PER_BLK;
    int tid = threadIdx.x;
    int nl = tid / 6, c = tid - nl * 6;
    int node = node0 + nl;
    int base = node0 * STRIDE;

    for (int i = tid; i < SEG_INTS; i += LH_THREADS)
        s_idx[i] = g_csr[base + i];
    __syncthreads();

    int beg = nl * STRIDE;
    int end = __ldg(&g_cur[node]) - base;

    __half2 z = __float2half2_rn(0.f);
    __half2 s0 = z, s1 = z, s2 = z, s3 = z;

    #pragma unroll 4
    for (int j = beg; j < end; ++j) {
        int s = s_idx[j];
        uint4 u = __ldg(h + (unsigned)s * PITCH_U4 + c);
        s0 = __hadd2(s0, *reinterpret_cast<const __half2*>(&u.x));
        s1 = __hadd2(s1, *reinterpret_cast<const __half2*>(&u.y));
        s2 = __hadd2(s2, *reinterpret_cast<const __half2*>(&u.z));
        s3 = __hadd2(s3, *reinterpret_cast<const __half2*>(&u.w));
    }

    if (FINAL) {
        float2 f0 = __half22float2(s0);
        float2 f1 = __half22float2(s1);
        float2 f2 = __half22float2(s2);
        float2 f3 = __half22float2(s3);
        outf[(unsigned)node * 12 + c * 2]     = make_float4(f0.x, f0.y, f1.x, f1.y);
        outf[(unsigned)node * 12 + c * 2 + 1] = make_float4(f2.x, f2.y, f3.x, f3.y);
    } else {
        __half2 p0 = __hmax2(s0, z);
        __half2 p1 = __hmax2(s1, z);
        __half2 p2 = __hmax2(s2, z);
        __half2 p3 = __hmax2(s3, z);
        uint4 u;
        u.x = *reinterpret_cast<unsigned*>(&p0);
        u.y = *reinterpret_cast<unsigned*>(&p1);
        u.z = *reinterpret_cast<unsigned*>(&p2);
        u.w = *reinterpret_cast<unsigned*>(&p3);
        outh[(unsigned)node * PITCH_U4 + c] = u;
    }
}

extern "C" void kernel_launch(void* const* d_in, const int* in_sizes, int n_in,
                              void* d_out, int out_size) {
    const float4* features = (const float4*)d_in[0];
    const int*    src      = (const int*)d_in[1];
    const int*    dst      = (const int*)d_in[2];
    float4*       out      = (float4*)d_out;
    int n_edges = in_sizes[1];

    uint4 *buf0 = nullptr, *buf1 = nullptr;
    cudaGetSymbolAddress((void**)&buf0, g_buf0);
    cudaGetSymbolAddress((void**)&buf1, g_buf1);

    // ---- bucket build (2 kernels) ----
    int n_quads = n_edges / 4;
    init_cur_kernel<<<(N_NODES + 255) / 256, 256>>>();
    fill_kernel<<<(n_quads / 2 + 255) / 256, 256>>>((const int4*)src,
                                                    (const int4*)dst, n_quads);

    // ---- 3 layers ----
    int nb = N_NODES / NODES_PER_BLK;   // 3125 exactly
    layer_f32_to_h<<<nb, L1_THREADS>>>(features, (uint2*)buf0);
    layer_h<false><<<nb, LH_THREADS>>>(buf0, buf1, nullptr);
    layer_h<true ><<<nb, LH_THREADS>>>(buf1, nullptr, out);
}

// round 16
// speedup vs baseline: 1.0096x; 1.0096x over previous
#include <cuda_runtime.h>
#include <cuda_fp16.h>
#include <cstdint>

#define N_NODES 100000
#define N_EDGES 1600000
#define D_FEAT 48
#define STRIDE 64                       // padded segment per node (max deg ~40)

#define NODES_PER_BLK 32
#define SEG_INTS (NODES_PER_BLK * STRIDE)   // 2048 staged indices / block

// ---- static device scratch (no allocation allowed) ----
__device__ int   g_cur[N_NODES];            // cursor; after fill = beg + deg
__device__ int   g_csr[N_NODES * STRIDE];   // padded per-node src lists
__device__ uint4 g_buf0[N_NODES * 6];       // half[N,48] = 96B/row (unpadded, R14)
__device__ uint4 g_buf1[N_NODES * 6];

// ---------------------------------------------------------------------------
// Bucket build: init cursors, then atomic scatter. No histogram, no scan.
// ---------------------------------------------------------------------------
__global__ void init_cur_kernel() {
    int i = blockIdx.x * blockDim.x + threadIdx.x;
    if (i < N_NODES) g_cur[i] = i * STRIDE;
}

// 4 int4 quads (16 edges) per thread; ALL atomics issued before any store,
// so 16 independent ATOMGs are in flight per thread (ATOMG lat ~318cyc).
__global__ void fill_kernel(const int4* __restrict__ src4,
                            const int4* __restrict__ dst4, int n_quads) {
    int q0 = (blockIdx.x * blockDim.x + threadIdx.x) * 4;
    int4 s[4], d[4];
    int  p[16];
    #pragma unroll
    for (int k = 0; k < 4; ++k) {
        int q = q0 + k;
        if (q < n_quads) { s[k] = src4[q]; d[k] = dst4[q]; }
        else             { s[k] = make_int4(0,0,0,0); d[k] = make_int4(-1,-1,-1,-1); }
    }
    #pragma unroll
    for (int k = 0; k < 4; ++k) {
        p[k*4+0] = (d[k].x >= 0) ? atomicAdd(&g_cur[d[k].x], 1) : -1;
        p[k*4+1] = (d[k].y >= 0) ? atomicAdd(&g_cur[d[k].y], 1) : -1;
        p[k*4+2] = (d[k].z >= 0) ? atomicAdd(&g_cur[d[k].z], 1) : -1;
        p[k*4+3] = (d[k].w >= 0) ? atomicAdd(&g_cur[d[k].w], 1) : -1;
    }
    #pragma unroll
    for (int k = 0; k < 4; ++k) {
        if (p[k*4+0] >= 0) g_csr[p[k*4+0]] = s[k].x;
        if (p[k*4+1] >= 0) g_csr[p[k*4+1]] = s[k].y;
        if (p[k*4+2] >= 0) g_csr[p[k*4+2]] = s[k].z;
        if (p[k*4+3] >= 0) g_csr[p[k*4+3]] = s[k].w;
    }
}

// ---------------------------------------------------------------------------
// Layer 1: fp32 features -> half buf (relu on store). fp32 accumulation.
// 32 nodes/block x 12 chunk-threads (proven geometry, unpadded output).
// ---------------------------------------------------------------------------
#define L1_THREADS (NODES_PER_BLK * 12)   // 384

__global__ void __launch_bounds__(L1_THREADS)
layer_f32_to_h(const float4* __restrict__ h, uint2* __restrict__ out) {
    __shared__ int s_idx[SEG_INTS];
    int node0 = blockIdx.x * NODES_PER_BLK;
    int tid = threadIdx.x;
    int nl = tid / 12, c = tid - nl * 12;
    int node = node0 + nl;
    int base = node0 * STRIDE;

    for (int i = tid; i < SEG_INTS; i += L1_THREADS)
        s_idx[i] = g_csr[base + i];
    __syncthreads();

    int beg = nl * STRIDE;              // block-relative
    int end = __ldg(&g_cur[node]) - base;

    float4 acc = make_float4(0.f, 0.f, 0.f, 0.f);
    #pragma unroll 8
    for (int j = beg; j < end; ++j) {
        int s = s_idx[j];
        float4 v = __ldg(h + (unsigned)s * 12 + c);
        acc.x += v.x; acc.y += v.y; acc.z += v.z; acc.w += v.w;
    }

    __half2 a = __floats2half2_rn(fmaxf(acc.x, 0.f), fmaxf(acc.y, 0.f));
    __half2 b = __floats2half2_rn(fmaxf(acc.z, 0.f), fmaxf(acc.w, 0.f));
    uint2 u;
    u.x = *reinterpret_cast<unsigned*>(&a);
    u.y = *reinterpret_cast<unsigned*>(&b);
    out[(unsigned)node * 12 + c] = u;
}

// ---------------------------------------------------------------------------
// Layers 2/3: half in, HADD2 accumulation, unroll 8 (8 LDGs in flight).
// FINAL=false -> HMAX2 relu + raw half store; FINAL=true -> fp32 out.
// 32 nodes/block x 6 chunk-threads (R14 geometry).
// ---------------------------------------------------------------------------
#define LH_THREADS (NODES_PER_BLK * 6)    // 192

template <bool FINAL>
__global__ void __launch_bounds__(LH_THREADS)
layer_h(const uint4* __restrict__ h, uint4* __restrict__ outh,
        float4* __restrict__ outf) {
    __shared__ int s_idx[SEG_INTS];
    int node0 = blockIdx.x * NODES_PER_BLK;
    int tid = threadIdx.x;
    int nl = tid / 6, c = tid - nl * 6;
    int node = node0 + nl;
    int base = node0 * STRIDE;

    for (int i = tid; i < SEG_INTS; i += LH_THREADS)
        s_idx[i] = g_csr[base + i];
    __syncthreads();

    int beg = nl * STRIDE;
    int end = __ldg(&g_cur[node]) - base;

    __half2 z = __float2half2_rn(0.f);
    __half2 s0 = z, s1 = z, s2 = z, s3 = z;

    #pragma unroll 8
    for (int j = beg; j < end; ++j) {
        int s = s_idx[j];
        uint4 u = __ldg(h + (unsigned)s * 6 + c);
        s0 = __hadd2(s0, *reinterpret_cast<const __half2*>(&u.x));
        s1 = __hadd2(s1, *reinterpret_cast<const __half2*>(&u.y));
        s2 = __hadd2(s2, *reinterpret_cast<const __half2*>(&u.z));
        s3 = __hadd2(s3, *reinterpret_cast<const __half2*>(&u.w));
    }

    if (FINAL) {
        float2 f0 = __half22float2(s0);
        float2 f1 = __half22float2(s1);
        float2 f2 = __half22float2(s2);
        float2 f3 = __half22float2(s3);
        outf[(unsigned)node * 12 + c * 2]     = make_float4(f0.x, f0.y, f1.x, f1.y);
        outf[(unsigned)node * 12 + c * 2 + 1] = make_float4(f2.x, f2.y, f3.x, f3.y);
    } else {
        __half2 p0 = __hmax2(s0, z);
        __half2 p1 = __hmax2(s1, z);
        __half2 p2 = __hmax2(s2, z);
        __half2 p3 = __hmax2(s3, z);
        uint4 u;
        u.x = *reinterpret_cast<unsigned*>(&p0);
        u.y = *reinterpret_cast<unsigned*>(&p1);
        u.z = *reinterpret_cast<unsigned*>(&p2);
        u.w = *reinterpret_cast<unsigned*>(&p3);
        outh[(unsigned)node * 6 + c] = u;
    }
}

extern "C" void kernel_launch(void* const* d_in, const int* in_sizes, int n_in,
                              void* d_out, int out_size) {
    const float4* features = (const float4*)d_in[0];
    const int*    src      = (const int*)d_in[1];
    const int*    dst      = (const int*)d_in[2];
    float4*       out      = (float4*)d_out;
    int n_edges = in_sizes[1];

    uint4 *buf0 = nullptr, *buf1 = nullptr;
    cudaGetSymbolAddress((void**)&buf0, g_buf0);
    cudaGetSymbolAddress((void**)&buf1, g_buf1);

    // ---- bucket build (2 kernels) ----
    int n_quads = n_edges / 4;
    int fill_threads = (n_quads + 3) / 4;
    init_cur_kernel<<<(N_NODES + 255) / 256, 256>>>();
    fill_kernel<<<(fill_threads + 255) / 256, 256>>>((const int4*)src,
                                                     (const int4*)dst, n_quads);

    // ---- 3 layers ----
    int nb = N_NODES / NODES_PER_BLK;   // 3125 exactly
    layer_f32_to_h<<<nb, L1_THREADS>>>(features, (uint2*)buf0);
    layer_h<false><<<nb, LH_THREADS>>>(buf0, buf1, nullptr);
    layer_h<true ><<<nb, LH_THREADS>>>(buf1, nullptr, out);
}

// round 17
// speedup vs baseline: 1.0264x; 1.0166x over previous
#include <cuda_runtime.h>
#include <cuda_fp16.h>
#include <cstdint>

#define N_NODES 100000
#define N_EDGES 1600000
#define D_FEAT 48
#define STRIDE 64                       // padded segment per node (max deg ~40)

#define NODES_PER_BLK 32
#define SEG_INTS (NODES_PER_BLK * STRIDE)   // 2048 staged indices / block

// ---- static device scratch (no allocation allowed) ----
__device__ int   g_cur[N_NODES];            // cursor; after fill = beg + deg
__device__ int   g_csr[N_NODES * STRIDE];   // padded per-node src lists
__device__ uint2 g_buf0[N_NODES * 12];      // half[N,48] = 96B/row (12 uint2)
__device__ uint2 g_buf1[N_NODES * 12];

// ---------------------------------------------------------------------------
// Bucket build: init cursors, then atomic scatter (R14-proven form).
// ---------------------------------------------------------------------------
__global__ void init_cur_kernel() {
    int i = blockIdx.x * blockDim.x + threadIdx.x;
    if (i < N_NODES) g_cur[i] = i * STRIDE;
}

// 2 int4 quads (8 edges) per thread: 8 independent atomics in flight.
__global__ void fill_kernel(const int4* __restrict__ src4,
                            const int4* __restrict__ dst4, int n_quads) {
    int q0 = (blockIdx.x * blockDim.x + threadIdx.x) * 2;
    #pragma unroll
    for (int k = 0; k < 2; ++k) {
        int q = q0 + k;
        if (q < n_quads) {
            int4 s = src4[q];
            int4 d = dst4[q];
            g_csr[atomicAdd(&g_cur[d.x], 1)] = s.x;
            g_csr[atomicAdd(&g_cur[d.y], 1)] = s.y;
            g_csr[atomicAdd(&g_cur[d.z], 1)] = s.z;
            g_csr[atomicAdd(&g_cur[d.w], 1)] = s.w;
        }
    }
}

// ---------------------------------------------------------------------------
// Layer 1: fp32 features -> half buf (relu on store). fp32 accumulation.
// 32 nodes/block x 12 chunk-threads (proven geometry).
// ---------------------------------------------------------------------------
#define L1_THREADS (NODES_PER_BLK * 12)   // 384

__global__ void __launch_bounds__(L1_THREADS)
layer_f32_to_h(const float4* __restrict__ h, uint2* __restrict__ out) {
    __shared__ int s_idx[SEG_INTS];
    int node0 = blockIdx.x * NODES_PER_BLK;
    int tid = threadIdx.x;
    int nl = tid / 12, c = tid - nl * 12;
    int node = node0 + nl;
    int base = node0 * STRIDE;

    for (int i = tid; i < SEG_INTS; i += L1_THREADS)
        s_idx[i] = g_csr[base + i];
    __syncthreads();

    int beg = nl * STRIDE;              // block-relative
    int end = __ldg(&g_cur[node]) - base;

    float4 acc = make_float4(0.f, 0.f, 0.f, 0.f);
    #pragma unroll 4
    for (int j = beg; j < end; ++j) {
        int s = s_idx[j];
        float4 v = __ldg(h + (unsigned)s * 12 + c);
        acc.x += v.x; acc.y += v.y; acc.z += v.z; acc.w += v.w;
    }

    __half2 a = __floats2half2_rn(fmaxf(acc.x, 0.f), fmaxf(acc.y, 0.f));
    __half2 b = __floats2half2_rn(fmaxf(acc.z, 0.f), fmaxf(acc.w, 0.f));
    uint2 u;
    u.x = *reinterpret_cast<unsigned*>(&a);
    u.y = *reinterpret_cast<unsigned*>(&b);
    out[(unsigned)node * 12 + c] = u;
}

// ---------------------------------------------------------------------------
// Layers 2/3: half in, 12 threads/node, uint2 (8B) gathers, HADD2 accum.
// Warp spans 2.67 nodes (less divergence), 600k warps (more latency hiding).
// FINAL=false -> HMAX2 relu + raw half store; FINAL=true -> fp32 out.
// ---------------------------------------------------------------------------
#define LH_THREADS (NODES_PER_BLK * 12)   // 384

template <bool FINAL>
__global__ void __launch_bounds__(LH_THREADS)
layer_h(const uint2* __restrict__ h, uint2* __restrict__ outh,
        float4* __restrict__ outf) {
    __shared__ int s_idx[SEG_INTS];
    int node0 = blockIdx.x * NODES_PER_BLK;
    int tid = threadIdx.x;
    int nl = tid / 12, c = tid - nl * 12;
    int node = node0 + nl;
    int base = node0 * STRIDE;

    for (int i = tid; i < SEG_INTS; i += LH_THREADS)
        s_idx[i] = g_csr[base + i];
    __syncthreads();

    int beg = nl * STRIDE;
    int end = __ldg(&g_cur[node]) - base;

    __half2 z = __float2half2_rn(0.f);
    __half2 s0 = z, s1 = z;

    #pragma unroll 4
    for (int j = beg; j < end; ++j) {
        int s = s_idx[j];
        uint2 u = __ldg(h + (unsigned)s * 12 + c);
        s0 = __hadd2(s0, *reinterpret_cast<const __half2*>(&u.x));
        s1 = __hadd2(s1, *reinterpret_cast<const __half2*>(&u.y));
    }

    if (FINAL) {
        float2 f0 = __half22float2(s0);
        float2 f1 = __half22float2(s1);
        outf[(unsigned)node * 12 + c] = make_float4(f0.x, f0.y, f1.x, f1.y);
    } else {
        __half2 p0 = __hmax2(s0, z);
        __half2 p1 = __hmax2(s1, z);
        uint2 u;
        u.x = *reinterpret_cast<unsigned*>(&p0);
        u.y = *reinterpret_cast<unsigned*>(&p1);
        outh[(unsigned)node * 12 + c] = u;
    }
}

extern "C" void kernel_launch(void* const* d_in, const int* in_sizes, int n_in,
                              void* d_out, int out_size) {
    const float4* features = (const float4*)d_in[0];
    const int*    src      = (const int*)d_in[1];
    const int*    dst      = (const int*)d_in[2];
    float4*       out      = (float4*)d_out;
    int n_edges = in_sizes[1];

    uint2 *buf0 = nullptr, *buf1 = nullptr;
    cudaGetSymbolAddress((void**)&buf0, g_buf0);
    cudaGetSymbolAddress((void**)&buf1, g_buf1);

    // ---- bucket build (2 kernels, R14 form) ----
    int n_quads = n_edges / 4;
    init_cur_kernel<<<(N_NODES + 255) / 256, 256>>>();
    fill_kernel<<<(n_quads / 2 + 255) / 256, 256>>>((const int4*)src,
                                                    (const int4*)dst, n_quads);

    // ---- 3 layers ----
    int nb = N_NODES / NODES_PER_BLK;   // 3125 exactly
    layer_f32_to_h<<<nb, L1_THREADS>>>(features, buf0);
    layer_h<false><<<nb, LH_THREADS>>>(buf0, buf1, nullptr);
    layer_h<true ><<<nb, LH_THREADS>>>(buf1, nullptr, out);
}